// round 2
// baseline (speedup 1.0000x reference)
#include <cuda_runtime.h>

// x: [N_NODES, 128] fp32  -> treated as [N_NODES, 32] float4 (rows 512B, aligned)
// src, dst: [E] int32  (JAX default x64-disabled demotes int64 -> int32)
// out: [E] fp32
//
// One warp per edge. Lane l loads float4 #l of the src row and dst row
// (perfectly coalesced 512B row reads -> 4x 128B sectors, zero waste),
// accumulates a partial dot, butterfly-reduces, lane 0 stores.

__global__ void __launch_bounds__(256) edge_dot_kernel(
    const float4* __restrict__ x,
    const int* __restrict__ src,
    const int* __restrict__ dst,
    float* __restrict__ out,
    int n_edges)
{
    const int warp_id = (blockIdx.x * blockDim.x + threadIdx.x) >> 5;
    const int lane    = threadIdx.x & 31;
    if (warp_id >= n_edges) return;

    const long long s = (long long)__ldg(&src[warp_id]);
    const long long d = (long long)__ldg(&dst[warp_id]);

    const float4 a = __ldg(&x[s * 32 + lane]);
    const float4 b = __ldg(&x[d * 32 + lane]);

    float sum = a.x * b.x;
    sum = fmaf(a.y, b.y, sum);
    sum = fmaf(a.z, b.z, sum);
    sum = fmaf(a.w, b.w, sum);

    #pragma unroll
    for (int off = 16; off > 0; off >>= 1)
        sum += __shfl_xor_sync(0xffffffffu, sum, off);

    if (lane == 0)
        out[warp_id] = sum;
}

extern "C" void kernel_launch(void* const* d_in, const int* in_sizes, int n_in,
                              void* d_out, int out_size)
{
    const float4* x   = (const float4*)d_in[0];
    const int*    src = (const int*)d_in[1];
    const int*    dst = (const int*)d_in[2];
    float*        out = (float*)d_out;

    const int n_edges = in_sizes[1];        // E = 1,000,000
    const int threads = 256;                // 8 warps/block
    const int warps_per_block = threads / 32;
    const int blocks = (n_edges + warps_per_block - 1) / warps_per_block;

    edge_dot_kernel<<<blocks, threads>>>(x, src, dst, out, n_edges);
}

// round 3
// speedup vs baseline: 1.7403x; 1.7403x over previous
#include <cuda_runtime.h>

// x:   [N_NODES, 128] fp32 -> [N_NODES, 32] float4 (rows 512B, 512B-aligned)
// src, dst: [E] int32 (JAX x64-disabled demotes int64 -> int32)
// out: [E] fp32
//
// Sub-warp tiling: 8 lanes per edge, 4 edges per warp.
// Each lane loads 4 float4 from the src row and 4 from the dst row
// (8 independent LDG.128 in flight; each load = one 128B sector, fully
// coalesced), accumulates 32 FMAs, then a 3-step xor-shuffle reduce
// within the 8-lane group. Lane 0 of each group stores its edge.

__global__ void __launch_bounds__(256) edge_dot_kernel(
    const float4* __restrict__ x,
    const int* __restrict__ src,
    const int* __restrict__ dst,
    float* __restrict__ out,
    int n_edges)
{
    const int warp_id = (blockIdx.x * blockDim.x + threadIdx.x) >> 5;
    const int lane    = threadIdx.x & 31;
    const int sub     = lane >> 3;      // edge slot within warp: 0..3
    const int sl      = lane & 7;       // lane within 8-lane group

    const int edge = warp_id * 4 + sub;
    if (edge >= n_edges) return;

    const long long s = (long long)__ldg(&src[edge]);
    const long long d = (long long)__ldg(&dst[edge]);

    const float4* __restrict__ xa = x + s * 32 + sl;
    const float4* __restrict__ xb = x + d * 32 + sl;

    // 8 independent 16B loads (MLP=8 per lane)
    float4 a0 = __ldg(xa +  0);
    float4 a1 = __ldg(xa +  8);
    float4 a2 = __ldg(xa + 16);
    float4 a3 = __ldg(xa + 24);
    float4 b0 = __ldg(xb +  0);
    float4 b1 = __ldg(xb +  8);
    float4 b2 = __ldg(xb + 16);
    float4 b3 = __ldg(xb + 24);

    // 4 independent partial sums for FMA ILP
    float s0 = a0.x * b0.x;  s0 = fmaf(a0.y, b0.y, s0);
    s0 = fmaf(a0.z, b0.z, s0);  s0 = fmaf(a0.w, b0.w, s0);
    float s1 = a1.x * b1.x;  s1 = fmaf(a1.y, b1.y, s1);
    s1 = fmaf(a1.z, b1.z, s1);  s1 = fmaf(a1.w, b1.w, s1);
    float s2 = a2.x * b2.x;  s2 = fmaf(a2.y, b2.y, s2);
    s2 = fmaf(a2.z, b2.z, s2);  s2 = fmaf(a2.w, b2.w, s2);
    float s3 = a3.x * b3.x;  s3 = fmaf(a3.y, b3.y, s3);
    s3 = fmaf(a3.z, b3.z, s3);  s3 = fmaf(a3.w, b3.w, s3);

    float sum = (s0 + s1) + (s2 + s3);

    // 3-step reduce within the 8-lane group
    sum += __shfl_xor_sync(0xffffffffu, sum, 4);
    sum += __shfl_xor_sync(0xffffffffu, sum, 2);
    sum += __shfl_xor_sync(0xffffffffu, sum, 1);

    if (sl == 0)
        out[edge] = sum;
}

extern "C" void kernel_launch(void* const* d_in, const int* in_sizes, int n_in,
                              void* d_out, int out_size)
{
    const float4* x   = (const float4*)d_in[0];
    const int*    src = (const int*)d_in[1];
    const int*    dst = (const int*)d_in[2];
    float*        out = (float*)d_out;

    const int n_edges = in_sizes[1];            // E = 1,000,000
    const int threads = 256;                    // 8 warps/block
    const int edges_per_block = (threads / 32) * 4;   // 32
    const int blocks = (n_edges + edges_per_block - 1) / edges_per_block;

    edge_dot_kernel<<<blocks, threads>>>(x, src, dst, out, n_edges);
}